// round 1
// baseline (speedup 1.0000x reference)
#include <cuda_runtime.h>
#include <cuda_bf16.h>

// Problem constants
// N=512, C=16, T=15, TP=T+1=16, H=32, DOUT=32, LEAK=0.2
// cols dimension for the big GEMMs: 512*16 = 8192

#define NN 512
#define TP 16
#define HH 32
#define KCOLS (NN * TP)   // 8192

// ---------------- scratch (device globals; no allocation allowed) ----------------
__device__ float g_XW1a[NN * TP * HH];   // [n][t][h] = sum_i x[n,i] W1[i,t,h]
__device__ float g_XW1b[NN * TP * HH];   // [n][t][h] = sum_i x[n,i] W1[i+16,t,h]
__device__ float g_XW2a[NN * TP * HH];
__device__ float g_XW2b[NN * TP * HH];
__device__ float g_Q[NN * HH];           // x @ W3
__device__ float g_QB[NN * TP];          // QB[n,t] = Q[n]·XW1b[n,t,:]
__device__ float g_RA[NN * TP];          // RA[n,t] = Q[n]·XW1a[n,t,:]
__device__ float g_QA[NN * KCOLS];       // QA[n, m*16+t] = Q[n]·XW1a[m,t,:]; reused as A1
__device__ float g_QC[NN * KCOLS];       // QC[n, m*16+t] = Q[n]·XW1b[m,t,:]; reused as A2
__device__ float g_L1[NN * NN];          // logits1 then s1 (row softmax)
__device__ float g_L2T[NN * NN];         // logits2 transposed, then s2t (row softmax)
__device__ float g_r1[NN * TP];          // r1ext
__device__ float g_c2[NN * TP];          // c2ext
__device__ float g_acc[NN * HH];         // GEMM accumulator (split-k atomics)

// ---------------- k1: XW1a/XW1b/XW2a/XW2b + Q ----------------
// grid 128 blocks x 256 thr; block handles 4 consecutive n
__global__ void k1_precompute(const float* __restrict__ x,
                              const float* __restrict__ W1,
                              const float* __restrict__ W2,
                              const float* __restrict__ W3) {
    int n0 = blockIdx.x * 4;
    __shared__ float xs[4][16];
    int tid = threadIdx.x;
    if (tid < 64) xs[tid / 16][tid % 16] = x[(n0 + tid / 16) * 16 + (tid % 16)];
    __syncthreads();

    for (int th = tid; th < 512; th += 256) {  // th = t*32+h
        float a1[4] = {0, 0, 0, 0}, b1[4] = {0, 0, 0, 0};
        float a2[4] = {0, 0, 0, 0}, b2[4] = {0, 0, 0, 0};
        for (int i = 0; i < 16; i++) {
            float w1a = W1[i * 512 + th];
            float w1b = W1[(i + 16) * 512 + th];
            float w2a = W2[i * 512 + th];
            float w2b = W2[(i + 16) * 512 + th];
#pragma unroll
            for (int j = 0; j < 4; j++) {
                float xv = xs[j][i];
                a1[j] += xv * w1a;
                b1[j] += xv * w1b;
                a2[j] += xv * w2a;
                b2[j] += xv * w2b;
            }
        }
#pragma unroll
        for (int j = 0; j < 4; j++) {
            g_XW1a[(n0 + j) * 512 + th] = a1[j];
            g_XW1b[(n0 + j) * 512 + th] = b1[j];
            g_XW2a[(n0 + j) * 512 + th] = a2[j];
            g_XW2b[(n0 + j) * 512 + th] = b2[j];
        }
    }
    if (tid < 32) {
        int h = tid;
#pragma unroll
        for (int j = 0; j < 4; j++) {
            float acc = 0.f;
            for (int i = 0; i < 16; i++) acc += xs[j][i] * W3[i * 32 + h];
            g_Q[(n0 + j) * 32 + h] = acc;
        }
    }
}

// ---------------- k1b: QB, RA ----------------
// grid 32 x 256; thread -> (n = b*16 + tid/16, t = tid%16)
__global__ void k1b_qbra() {
    int n = blockIdx.x * 16 + threadIdx.x / 16;
    int t = threadIdx.x % 16;
    const float* q = g_Q + n * 32;
    const float* wa = g_XW1a + n * 512 + t * 32;
    const float* wb = g_XW1b + n * 512 + t * 32;
    float ra = 0.f, qb = 0.f;
#pragma unroll
    for (int h = 0; h < 32; h++) {
        float qv = q[h];
        ra += qv * wa[h];
        qb += qv * wb[h];
    }
    g_RA[n * 16 + t] = ra;
    g_QB[n * 16 + t] = qb;
}

// ---------------- k2: QA/QC big GEMM [512x32]@[32x8192] x2 ----------------
// grid (64 colTiles, 4 nTiles), 256 thr. Each thread owns one col (of 128),
// its XW rows in registers, loops 64 n.
__global__ void k2_qaqc() {
    __shared__ float Qs[128][32];
    int colg = blockIdx.x * 128 + (threadIdx.x & 127);
    int ngrp = threadIdx.x >> 7;  // 0 or 1
    int nbase = blockIdx.y * 128;

    for (int idx = threadIdx.x; idx < 128 * 32; idx += 256)
        Qs[idx >> 5][idx & 31] = g_Q[(nbase + (idx >> 5)) * 32 + (idx & 31)];

    float wa[32], wb[32];
    const float4* pa = (const float4*)(g_XW1a + colg * 32);
    const float4* pb = (const float4*)(g_XW1b + colg * 32);
#pragma unroll
    for (int v = 0; v < 8; v++) {
        float4 fa = pa[v], fb = pb[v];
        wa[4 * v + 0] = fa.x; wa[4 * v + 1] = fa.y; wa[4 * v + 2] = fa.z; wa[4 * v + 3] = fa.w;
        wb[4 * v + 0] = fb.x; wb[4 * v + 1] = fb.y; wb[4 * v + 2] = fb.z; wb[4 * v + 3] = fb.w;
    }
    __syncthreads();

    for (int nl = 0; nl < 64; nl++) {
        int nrow = ngrp * 64 + nl;
        float acc1 = 0.f, acc2 = 0.f;
#pragma unroll
        for (int h = 0; h < 32; h++) {
            float qv = Qs[nrow][h];
            acc1 += qv * wa[h];
            acc2 += qv * wb[h];
        }
        int n = nbase + nrow;
        g_QA[n * KCOLS + colg] = acc1;
        g_QC[n * KCOLS + colg] = acc2;
    }
}

// ---------------- k4: logits1 and logits2^T ----------------
// grid 512 (per row a), 256 thr, each thread 2 b's
__global__ void k4_logits(const float* __restrict__ adj) {
    int a = blockIdx.x;
    __shared__ float QBs[16], RAs[16];
    if (threadIdx.x < 16) {
        QBs[threadIdx.x] = g_QB[a * 16 + threadIdx.x];
        RAs[threadIdx.x] = g_RA[a * 16 + threadIdx.x];
    }
    __syncthreads();
    for (int b = threadIdx.x; b < 512; b += 256) {
        const float* arow = adj + (a * 512 + b) * 15;
        const float* acol = adj + (b * 512 + a) * 15;
        const float* qa = g_QA + a * KCOLS + b * 16;
        const float* qc = g_QC + a * KCOLS + b * 16;
        float l1 = 0.f, l2 = 0.f;
#pragma unroll
        for (int t = 0; t < 15; t++) {
            float ar = arow[t], ac = acol[t];
            l1 += ar * qa[t] + ac * QBs[t];
            l2 += ac * RAs[t] + ar * qc[t];
        }
        if (b == a) {
            l1 += qa[15] + QBs[15];
            l2 += RAs[15] + qc[15];
        }
        g_L1[a * 512 + b] = l1;
        g_L2T[a * 512 + b] = l2;
    }
}

// ---------------- k5: in-place row softmax of L1 (rows 0-511) and L2T (512-1023) ----------------
__global__ void k5_softmax() {
    int r = blockIdx.x;
    float* row = (r < 512) ? (g_L1 + r * 512) : (g_L2T + (r - 512) * 512);
    int tid = threadIdx.x;  // 256
    __shared__ float red[8];
    float v0 = row[tid], v1 = row[tid + 256];
    float m = fmaxf(v0, v1);
#pragma unroll
    for (int o = 16; o; o >>= 1) m = fmaxf(m, __shfl_xor_sync(0xffffffffu, m, o));
    if ((tid & 31) == 0) red[tid >> 5] = m;
    __syncthreads();
    float bm = red[0];
#pragma unroll
    for (int i = 1; i < 8; i++) bm = fmaxf(bm, red[i]);
    float e0 = __expf(v0 - bm), e1 = __expf(v1 - bm);
    float s = e0 + e1;
#pragma unroll
    for (int o = 16; o; o >>= 1) s += __shfl_xor_sync(0xffffffffu, s, o);
    __syncthreads();
    if ((tid & 31) == 0) red[tid >> 5] = s;
    __syncthreads();
    float bs = red[0] + red[1] + red[2] + red[3] + red[4] + red[5] + red[6] + red[7];
    float inv = 1.0f / bs;
    row[tid] = e0 * inv;
    row[tid + 256] = e1 * inv;
}

// ---------------- k6: build A1 (into g_QA), A2 (into g_QC), r1ext, c2ext ----------------
// grid 512 (per row a), 256 thr
__global__ void k6_abuild(const float* __restrict__ adj) {
    int a = blockIdx.x;
    __shared__ float s1s[512], s2s[512];
    __shared__ float sr1[16], sc2[16];
    int tid = threadIdx.x;
    s1s[tid] = g_L1[a * 512 + tid];
    s1s[tid + 256] = g_L1[a * 512 + tid + 256];
    s2s[tid] = g_L2T[a * 512 + tid];
    s2s[tid + 256] = g_L2T[a * 512 + tid + 256];
    if (tid < 16) { sr1[tid] = 0.f; sc2[tid] = 0.f; }
    __syncthreads();

    // Phase A: A1[a, m*16+t] = s1[a,m]*adj[a,m,t]; t=15 diag slot
    for (int idx = tid; idx < KCOLS; idx += 256) {
        int m = idx >> 4, t = idx & 15;
        float oA, oB;
        if (t < 15) {
            float av = adj[(a * 512 + m) * 15 + t];
            oA = s1s[m] * av;
            oB = s2s[m] * av;
        } else {
            oA = (m == a) ? s1s[a] : 0.f;
            oB = (m == a) ? s2s[a] : 0.f;
        }
        g_QA[a * KCOLS + idx] = oA;  // A1
        g_QC[a * KCOLS + idx] = oB;  // A2
    }

    // Phase B: r1[a,t] = sum_m s1[a,m]*adj[m,a,t]; c2[a,t] = sum_m s2t[a,m]*adj[m,a,t]
    float r1a[15], c2a[15];
#pragma unroll
    for (int t = 0; t < 15; t++) { r1a[t] = 0.f; c2a[t] = 0.f; }
    for (int m = tid; m < 512; m += 256) {
        const float* av = adj + (m * 512 + a) * 15;
        float w1 = s1s[m], w2 = s2s[m];
#pragma unroll
        for (int t = 0; t < 15; t++) {
            float v = av[t];
            r1a[t] += w1 * v;
            c2a[t] += w2 * v;
        }
    }
#pragma unroll
    for (int t = 0; t < 15; t++) {
#pragma unroll
        for (int o = 16; o; o >>= 1) {
            r1a[t] += __shfl_xor_sync(0xffffffffu, r1a[t], o);
            c2a[t] += __shfl_xor_sync(0xffffffffu, c2a[t], o);
        }
    }
    if ((tid & 31) == 0) {
#pragma unroll
        for (int t = 0; t < 15; t++) {
            atomicAdd(&sr1[t], r1a[t]);
            atomicAdd(&sc2[t], c2a[t]);
        }
    }
    __syncthreads();
    if (tid < 15) {
        g_r1[a * 16 + tid] = sr1[tid];
        g_c2[a * 16 + tid] = sc2[tid];
    }
    if (tid == 15) {
        g_r1[a * 16 + 15] = s1s[a];   // diag slot
        g_c2[a * 16 + 15] = s2s[a];
    }
}

// ---------------- kzero: clear accumulator ----------------
__global__ void kzero() { g_acc[blockIdx.x * 256 + threadIdx.x] = 0.f; }  // grid 64

// ---------------- k7: G1 = A1@XW2a, G2 = A2@XW2b, split-k atomics ----------------
// grid (8 ksplits, 32 ntiles of 16), 256 thr, 48KB smem
__global__ void k7_gemm() {
    __shared__ float As1[128][16], As2[128][16];
    __shared__ float Bs1[128][32], Bs2[128][32];
    int n0 = blockIdx.y * 16;
    int k0 = blockIdx.x * 1024;
    int tid = threadIdx.x;
    int d = tid & 31;
    int grp = tid >> 5;          // 0..7
    bool g2 = grp >= 4;
    int ksub = (grp & 3) * 32;   // each group covers 32 kk of the 128-chunk
    float acc[16];
#pragma unroll
    for (int i = 0; i < 16; i++) acc[i] = 0.f;

    for (int kc = 0; kc < 1024; kc += 128) {
        __syncthreads();
        for (int idx = tid; idx < 2048; idx += 256) {
            int nl = idx >> 7, kk = idx & 127;
            As1[kk][nl] = g_QA[(n0 + nl) * KCOLS + k0 + kc + kk];
            As2[kk][nl] = g_QC[(n0 + nl) * KCOLS + k0 + kc + kk];
        }
        for (int idx = tid; idx < 4096; idx += 256) {
            int kk = idx >> 5, dd = idx & 31;
            Bs1[kk][dd] = g_XW2a[(k0 + kc + kk) * 32 + dd];
            Bs2[kk][dd] = g_XW2b[(k0 + kc + kk) * 32 + dd];
        }
        __syncthreads();
        const float(*As)[16] = g2 ? As2 : As1;
        const float(*Bs)[32] = g2 ? Bs2 : Bs1;
#pragma unroll 4
        for (int kk = ksub; kk < ksub + 32; kk++) {
            float bv = Bs[kk][d];
#pragma unroll
            for (int nl = 0; nl < 16; nl++) acc[nl] += As[kk][nl] * bv;
        }
    }
#pragma unroll
    for (int nl = 0; nl < 16; nl++) atomicAdd(&g_acc[(n0 + nl) * 32 + d], acc[nl]);
}

// ---------------- k7b: epilogue (small per-row terms + lrelu) ----------------
__global__ void k7b_epilogue(float* __restrict__ out) {
    int idx = blockIdx.x * 256 + threadIdx.x;  // grid 64 -> 16384
    int n = idx >> 5, d = idx & 31;
    float acc = g_acc[idx];
    const float* r1 = g_r1 + n * 16;
    const float* c2 = g_c2 + n * 16;
    const float* wb = g_XW2b + n * 512 + d;  // stride 32 over t
    const float* wa = g_XW2a + n * 512 + d;
#pragma unroll
    for (int t = 0; t < 16; t++) acc += r1[t] * wb[t * 32] + c2[t] * wa[t * 32];
    out[idx] = fmaxf(acc, 0.2f * acc);
}

// ---------------- launch ----------------
extern "C" void kernel_launch(void* const* d_in, const int* in_sizes, int n_in,
                              void* d_out, int out_size) {
    const float* x   = (const float*)d_in[0];   // [512,16]
    const float* adj = (const float*)d_in[1];   // [512,512,15]
    const float* W1  = (const float*)d_in[2];   // [32,16,32]
    const float* W2  = (const float*)d_in[3];   // [32,16,32]
    const float* W3  = (const float*)d_in[4];   // [16,32]
    float* out = (float*)d_out;                 // [512,32]
    (void)in_sizes; (void)n_in; (void)out_size;

    k1_precompute<<<128, 256>>>(x, W1, W2, W3);
    k1b_qbra<<<32, 256>>>();
    k2_qaqc<<<dim3(64, 4), 256>>>();
    kzero<<<64, 256>>>();
    k4_logits<<<512, 256>>>(adj);
    k5_softmax<<<1024, 256>>>();
    k6_abuild<<<512, 256>>>(adj);
    k7_gemm<<<dim3(8, 32), 256>>>();
    k7b_epilogue<<<64, 256>>>(out);
}

// round 2
// speedup vs baseline: 1.6151x; 1.6151x over previous
#include <cuda_runtime.h>

#define NN 512
#define TP 16
#define KCOLS 8192

typedef unsigned long long ull;

// ---------- f32x2 packed helpers (FFMA2: 2x fp32 rate, only reachable via PTX) ----------
__device__ __forceinline__ ull pk2(float lo, float hi) {
    ull r; asm("mov.b64 %0, {%1, %2};" : "=l"(r) : "f"(lo), "f"(hi)); return r;
}
__device__ __forceinline__ void upk2(float& lo, float& hi, ull v) {
    asm("mov.b64 {%0, %1}, %2;" : "=f"(lo), "=f"(hi) : "l"(v));
}
__device__ __forceinline__ void ffma2(ull& acc, ull a, ull b) {
    asm("fma.rn.f32x2 %0, %1, %2, %0;" : "+l"(acc) : "l"(a), "l"(b));
}

// ---------------- scratch ----------------
__device__ float g_XW1a[NN * TP * 32];
__device__ float g_XW1b[NN * TP * 32];
__device__ float g_XW2a[NN * TP * 32];
__device__ float g_XW2b[NN * TP * 32];
__device__ float g_Q[NN * 32];
__device__ float g_QB[NN * TP];
__device__ float g_RA[NN * TP];
__device__ float g_L1[NN * NN];    // logits1 -> s1
__device__ float g_L2T[NN * NN];   // logits2^T -> s2^T
__device__ float g_r1[NN * TP];
__device__ float g_c2[NN * TP];
__device__ float g_acc[NN * 32];

// ---------------- k1: XW1a/b, XW2a/b, Q, QB, RA ----------------
__global__ void k1_precompute(const float* __restrict__ x,
                              const float* __restrict__ W1,
                              const float* __restrict__ W2,
                              const float* __restrict__ W3) {
    int n0 = blockIdx.x * 4;
    __shared__ float xs[4][16];
    int tid = threadIdx.x;
    if (tid < 64) xs[tid / 16][tid % 16] = x[(n0 + tid / 16) * 16 + (tid % 16)];
    __syncthreads();

    for (int th = tid; th < 512; th += 256) {
        float a1[4] = {0,0,0,0}, b1[4] = {0,0,0,0};
        float a2[4] = {0,0,0,0}, b2[4] = {0,0,0,0};
        for (int i = 0; i < 16; i++) {
            float w1a = W1[i * 512 + th];
            float w1b = W1[(i + 16) * 512 + th];
            float w2a = W2[i * 512 + th];
            float w2b = W2[(i + 16) * 512 + th];
#pragma unroll
            for (int j = 0; j < 4; j++) {
                float xv = xs[j][i];
                a1[j] += xv * w1a; b1[j] += xv * w1b;
                a2[j] += xv * w2a; b2[j] += xv * w2b;
            }
        }
#pragma unroll
        for (int j = 0; j < 4; j++) {
            g_XW1a[(n0 + j) * 512 + th] = a1[j];
            g_XW1b[(n0 + j) * 512 + th] = b1[j];
            g_XW2a[(n0 + j) * 512 + th] = a2[j];
            g_XW2b[(n0 + j) * 512 + th] = b2[j];
        }
    }
    if (tid < 32) {
#pragma unroll
        for (int j = 0; j < 4; j++) {
            float acc = 0.f;
            for (int i = 0; i < 16; i++) acc += xs[j][i] * W3[i * 32 + tid];
            g_Q[(n0 + j) * 32 + tid] = acc;
        }
    }
    __syncthreads();   // make g_XW1*, g_Q visible within block
    if (tid < 64) {
        int n = n0 + tid / 16, t = tid % 16;
        const float* q  = g_Q + n * 32;
        const float* wa = g_XW1a + n * 512 + t * 32;
        const float* wb = g_XW1b + n * 512 + t * 32;
        float ra = 0.f, qb = 0.f;
#pragma unroll
        for (int h = 0; h < 32; h++) { float qv = q[h]; ra += qv * wa[h]; qb += qv * wb[h]; }
        g_RA[n * 16 + t] = ra;
        g_QB[n * 16 + t] = qb;
    }
}

// ---------------- k2: fused logits (no QA/QC materialization) + zero accumulators ----------------
// grid (16,16): x = b-tile, y = a-tile. 512 threads: tid -> (bl = tid>>4, t = tid&15)
__global__ void __launch_bounds__(512) k2_logits(const float* __restrict__ adj) {
    int tid = threadIdx.x;
    int bid = blockIdx.y * 16 + blockIdx.x;
    // fold accumulator zeroing into this kernel (saves a launch)
    if (bid < 32)      g_acc[bid * 512 + tid] = 0.f;
    else if (bid < 48) g_r1[(bid - 32) * 512 + tid] = 0.f;
    else if (bid < 64) g_c2[(bid - 48) * 512 + tid] = 0.f;

    int a0 = blockIdx.y * 32, b0 = blockIdx.x * 32;
    int bl = tid >> 4, t = tid & 15;
    int bg = b0 + bl;

    __shared__ ull   Qs[32][16];    // packed Q pairs for a-tile
    __shared__ float QBs[32][16], RAs[32][16];
    {
        int a = tid >> 4, p = tid & 15;
        float2 v = *((const float2*)(g_Q + (a0 + a) * 32) + p);
        Qs[a][p]  = pk2(v.x, v.y);
        QBs[a][p] = g_QB[(a0 + a) * 16 + p];
        RAs[a][p] = g_RA[(a0 + a) * 16 + p];
    }
    // per-thread XW1 column (b=bg, t) in registers, packed
    ull wa[16], wb[16];
    {
        const float4* pa = (const float4*)(g_XW1a + (bg * 16 + t) * 32);
        const float4* pb = (const float4*)(g_XW1b + (bg * 16 + t) * 32);
#pragma unroll
        for (int v = 0; v < 8; v++) {
            float4 fa = pa[v], fb = pb[v];
            wa[2 * v] = pk2(fa.x, fa.y); wa[2 * v + 1] = pk2(fa.z, fa.w);
            wb[2 * v] = pk2(fb.x, fb.y); wb[2 * v + 1] = pk2(fb.z, fb.w);
        }
    }
    __syncthreads();

    bool hasT = (t < 15);
    const float* pR = adj + ((long)a0 * 512 + bg) * 15 + t;  // + al*7680
    const float* pC = adj + ((long)bg * 512 + a0) * 15 + t;  // + al*15

    for (int al = 0; al < 32; al++) {
        int ag = a0 + al;
        ull acc1 = 0ull, acc2 = 0ull;
        const ulonglong2* qrow = (const ulonglong2*)Qs[al];
#pragma unroll
        for (int j = 0; j < 8; j++) {
            ulonglong2 q = qrow[j];
            ffma2(acc1, q.x, wa[2 * j]);
            ffma2(acc1, q.y, wa[2 * j + 1]);
            ffma2(acc2, q.x, wb[2 * j]);
            ffma2(acc2, q.y, wb[2 * j + 1]);
        }
        float lo, hi;
        upk2(lo, hi, acc1); float p1 = lo + hi;  // Q[ag]·XW1a[bg,t,:]
        upk2(lo, hi, acc2); float p2 = lo + hi;  // Q[ag]·XW1b[bg,t,:]

        float l1p, l2p;
        if (hasT) {
            float ar = pR[al * 7680];
            float ac = pC[al * 15];
            l1p = ar * p1 + ac * QBs[al][t];
            l2p = ac * RAs[al][t] + ar * p2;
        } else {
            bool dg = (ag == bg);
            l1p = dg ? (p1 + QBs[al][15]) : 0.f;
            l2p = dg ? (RAs[al][15] + p2) : 0.f;
        }
#pragma unroll
        for (int o = 8; o; o >>= 1) {
            l1p += __shfl_xor_sync(0xffffffffu, l1p, o);
            l2p += __shfl_xor_sync(0xffffffffu, l2p, o);
        }
        if (t == 0) {
            g_L1[ag * 512 + bg]  = l1p;
            g_L2T[ag * 512 + bg] = l2p;
        }
    }
}

// ---------------- k5: row softmax (L1 rows 0-511, L2T rows 512-1023) ----------------
__global__ void k5_softmax() {
    int r = blockIdx.x;
    float* row = (r < 512) ? (g_L1 + r * 512) : (g_L2T + (r - 512) * 512);
    int tid = threadIdx.x;
    __shared__ float red[8];
    float v0 = row[tid], v1 = row[tid + 256];
    float m = fmaxf(v0, v1);
#pragma unroll
    for (int o = 16; o; o >>= 1) m = fmaxf(m, __shfl_xor_sync(0xffffffffu, m, o));
    if ((tid & 31) == 0) red[tid >> 5] = m;
    __syncthreads();
    float bm = red[0];
#pragma unroll
    for (int i = 1; i < 8; i++) bm = fmaxf(bm, red[i]);
    float e0 = __expf(v0 - bm), e1 = __expf(v1 - bm);
    float s = e0 + e1;
#pragma unroll
    for (int o = 16; o; o >>= 1) s += __shfl_xor_sync(0xffffffffu, s, o);
    __syncthreads();
    if ((tid & 31) == 0) red[tid >> 5] = s;
    __syncthreads();
    float bs = red[0] + red[1] + red[2] + red[3] + red[4] + red[5] + red[6] + red[7];
    float inv = 1.0f / bs;
    row[tid] = e0 * inv;
    row[tid + 256] = e1 * inv;
}

// ---------------- k7: fused A-build + GEMM + r1/c2 reductions ----------------
// grid (16 ksplits over m, 16 a-tiles of 32), 256 threads
__global__ void __launch_bounds__(256) k7_fused(const float* __restrict__ adj) {
    int m0 = blockIdx.x * 32;
    int a0 = blockIdx.y * 32;
    int tid = threadIdx.x;

    __shared__ float s1s[32][33], s2s[32][33];
    __shared__ float As1[64][32], As2[64][32];
    __shared__ float Bs1[64][32], Bs2[64][32];
    __shared__ float adjS[32][61];   // [a][ml*15+t] staging, stride 61 (coprime w/ 32)

#pragma unroll
    for (int j = 0; j < 4; j++) {
        int idx = tid + j * 256;
        int a = idx >> 5, ml = idx & 31;
        s1s[a][ml] = g_L1[(a0 + a) * 512 + m0 + ml];
        s2s[a][ml] = g_L2T[(a0 + a) * 512 + m0 + ml];
    }
    __syncthreads();

    // r1/c2 partials over this block's m-range (adj column access, coalesced)
    {
        int a = tid >> 3, tp = tid & 7;
        int t0 = tp * 2;
        int ag = a0 + a;
        bool hasT1 = (t0 + 1 < 15);
        float r0 = 0.f, r1v = 0.f, c0 = 0.f, c1v = 0.f;
        for (int ml = 0; ml < 32; ml++) {
            const float* base = adj + ((long)(m0 + ml) * 512 + ag) * 15;
            float v0 = base[t0];
            float v1 = hasT1 ? base[t0 + 1] : 0.f;
            float w1 = s1s[a][ml], w2 = s2s[a][ml];
            r0 += w1 * v0; r1v += w1 * v1;
            c0 += w2 * v0; c1v += w2 * v1;
        }
        atomicAdd(&g_r1[ag * 16 + t0], r0);
        atomicAdd(&g_c2[ag * 16 + t0], c0);
        if (hasT1) {
            atomicAdd(&g_r1[ag * 16 + t0 + 1], r1v);
            atomicAdd(&g_c2[ag * 16 + t0 + 1], c1v);
        } else if (ag >= m0 && ag < m0 + 32) {   // diag slot t=15
            atomicAdd(&g_r1[ag * 16 + 15], s1s[a][ag - m0]);
            atomicAdd(&g_c2[ag * 16 + 15], s2s[a][ag - m0]);
        }
    }

    // main GEMM: out[a,d] += sum_k A1[a,k] XW2a[k,d] + A2[a,k] XW2b[k,d]
    int d = tid & 31;
    int a4 = (tid >> 5) * 4;
    ull acc01 = 0ull, acc23 = 0ull;

    for (int mc = 0; mc < 8; mc++) {
        int mb = m0 + mc * 4;
        int kbase = mb * 16;
        __syncthreads();
        // stage adj rows (coalesced: 60 contiguous floats per a)
#pragma unroll
        for (int j = 0; j < 8; j++) {
            int idx = tid + j * 256;
            int a = idx >> 6, r = idx & 63;
            if (r < 60) adjS[a][r] = adj[(long)(a0 + a) * 7680 + mb * 15 + r];
        }
        __syncthreads();
        // build A tiles (conflict-free via padded strides)
#pragma unroll
        for (int j = 0; j < 8; j++) {
            int idx = tid + j * 256;
            int a = idx & 31, kk = idx >> 5;
            int mls = kk >> 4, t = kk & 15;
            float v1, v2;
            float sv1 = s1s[a][mc * 4 + mls], sv2 = s2s[a][mc * 4 + mls];
            if (t < 15) {
                float av = adjS[a][mls * 15 + t];
                v1 = sv1 * av; v2 = sv2 * av;
            } else {
                bool dg = (mb + mls == a0 + a);
                v1 = dg ? sv1 : 0.f;
                v2 = dg ? sv2 : 0.f;
            }
            As1[kk][a] = v1;
            As2[kk][a] = v2;
        }
        // B panels
#pragma unroll
        for (int j = 0; j < 8; j++) {
            int idx = tid + j * 256;
            int kk = idx >> 5, dd = idx & 31;
            Bs1[kk][dd] = g_XW2a[(kbase + kk) * 32 + dd];
            Bs2[kk][dd] = g_XW2b[(kbase + kk) * 32 + dd];
        }
        __syncthreads();
#pragma unroll 8
        for (int kk = 0; kk < 64; kk++) {
            float b1 = Bs1[kk][d], b2 = Bs2[kk][d];
            ull b1p = pk2(b1, b1), b2p = pk2(b2, b2);
            ulonglong2 a1 = *(const ulonglong2*)&As1[kk][a4];
            ulonglong2 a2 = *(const ulonglong2*)&As2[kk][a4];
            ffma2(acc01, a1.x, b1p);
            ffma2(acc23, a1.y, b1p);
            ffma2(acc01, a2.x, b2p);
            ffma2(acc23, a2.y, b2p);
        }
    }
    float f0, f1, f2, f3;
    upk2(f0, f1, acc01);
    upk2(f2, f3, acc23);
    atomicAdd(&g_acc[(a0 + a4 + 0) * 32 + d], f0);
    atomicAdd(&g_acc[(a0 + a4 + 1) * 32 + d], f1);
    atomicAdd(&g_acc[(a0 + a4 + 2) * 32 + d], f2);
    atomicAdd(&g_acc[(a0 + a4 + 3) * 32 + d], f3);
}

// ---------------- k7b: epilogue ----------------
__global__ void k7b_epilogue(float* __restrict__ out) {
    int idx = blockIdx.x * 256 + threadIdx.x;
    int n = idx >> 5, d = idx & 31;
    float acc = g_acc[idx];
    const float* r1 = g_r1 + n * 16;
    const float* c2 = g_c2 + n * 16;
    const float* wb = g_XW2b + n * 512 + d;
    const float* wa = g_XW2a + n * 512 + d;
#pragma unroll
    for (int t = 0; t < 16; t++) acc += r1[t] * wb[t * 32] + c2[t] * wa[t * 32];
    out[idx] = fmaxf(acc, 0.2f * acc);
}

// ---------------- launch ----------------
extern "C" void kernel_launch(void* const* d_in, const int* in_sizes, int n_in,
                              void* d_out, int out_size) {
    const float* x   = (const float*)d_in[0];
    const float* adj = (const float*)d_in[1];
    const float* W1  = (const float*)d_in[2];
    const float* W2  = (const float*)d_in[3];
    const float* W3  = (const float*)d_in[4];
    float* out = (float*)d_out;
    (void)in_sizes; (void)n_in; (void)out_size;

    k1_precompute<<<128, 256>>>(x, W1, W2, W3);
    k2_logits<<<dim3(16, 16), 512>>>(adj);
    k5_softmax<<<1024, 256>>>();
    k7_fused<<<dim3(16, 16), 256>>>(adj);
    k7b_epilogue<<<64, 256>>>(out);
}

// round 3
// speedup vs baseline: 1.7996x; 1.1142x over previous
#include <cuda_runtime.h>

#define NN 512
#define TP 16

typedef unsigned long long ull;

// ---------- f32x2 packed helpers (FFMA2: 2x fp32 rate, only reachable via PTX) ----------
__device__ __forceinline__ ull pk2(float lo, float hi) {
    ull r; asm("mov.b64 %0, {%1, %2};" : "=l"(r) : "f"(lo), "f"(hi)); return r;
}
__device__ __forceinline__ void upk2(float& lo, float& hi, ull v) {
    asm("mov.b64 {%0, %1}, %2;" : "=f"(lo), "=f"(hi) : "l"(v));
}
__device__ __forceinline__ void ffma2(ull& acc, ull a, ull b) {
    asm("fma.rn.f32x2 %0, %1, %2, %0;" : "+l"(acc) : "l"(a), "l"(b));
}

// ---------------- scratch ----------------
__device__ float g_XW1a[NN * TP * 32];
__device__ float g_XW1b[NN * TP * 32];
__device__ float g_XW2a[NN * TP * 32];
__device__ float g_XW2b[NN * TP * 32];
__device__ float g_Q[NN * 32];
__device__ float g_QB[NN * TP];
__device__ float g_RA[NN * TP];
__device__ float g_L1[NN * NN];    // logits1 -> s1
__device__ float g_L2T[NN * NN];   // logits2^T -> s2^T
__device__ float g_r1[NN * TP];
__device__ float g_c2[NN * TP];
__device__ float g_acc[NN * 32];

// ---------------- k1: XW1a/b, XW2a/b, Q, QB, RA ----------------
__global__ void k1_precompute(const float* __restrict__ x,
                              const float* __restrict__ W1,
                              const float* __restrict__ W2,
                              const float* __restrict__ W3) {
    int n0 = blockIdx.x * 4;
    __shared__ float xs[4][16];
    int tid = threadIdx.x;
    if (tid < 64) xs[tid / 16][tid % 16] = x[(n0 + tid / 16) * 16 + (tid % 16)];
    __syncthreads();

    for (int th = tid; th < 512; th += 256) {
        float a1[4] = {0,0,0,0}, b1[4] = {0,0,0,0};
        float a2[4] = {0,0,0,0}, b2[4] = {0,0,0,0};
        for (int i = 0; i < 16; i++) {
            float w1a = W1[i * 512 + th];
            float w1b = W1[(i + 16) * 512 + th];
            float w2a = W2[i * 512 + th];
            float w2b = W2[(i + 16) * 512 + th];
#pragma unroll
            for (int j = 0; j < 4; j++) {
                float xv = xs[j][i];
                a1[j] += xv * w1a; b1[j] += xv * w1b;
                a2[j] += xv * w2a; b2[j] += xv * w2b;
            }
        }
#pragma unroll
        for (int j = 0; j < 4; j++) {
            g_XW1a[(n0 + j) * 512 + th] = a1[j];
            g_XW1b[(n0 + j) * 512 + th] = b1[j];
            g_XW2a[(n0 + j) * 512 + th] = a2[j];
            g_XW2b[(n0 + j) * 512 + th] = b2[j];
        }
    }
    if (tid < 32) {
#pragma unroll
        for (int j = 0; j < 4; j++) {
            float acc = 0.f;
            for (int i = 0; i < 16; i++) acc += xs[j][i] * W3[i * 32 + tid];
            g_Q[(n0 + j) * 32 + tid] = acc;
        }
    }
    __syncthreads();
    if (tid < 64) {
        int n = n0 + tid / 16, t = tid % 16;
        const float* q  = g_Q + n * 32;
        const float* wa = g_XW1a + n * 512 + t * 32;
        const float* wb = g_XW1b + n * 512 + t * 32;
        float ra = 0.f, qb = 0.f;
#pragma unroll
        for (int h = 0; h < 32; h++) { float qv = q[h]; ra += qv * wa[h]; qb += qv * wb[h]; }
        g_RA[n * 16 + t] = ra;
        g_QB[n * 16 + t] = qb;
    }
}

// ---------------- k2: fused logits + zero accumulators ----------------
__global__ void __launch_bounds__(512) k2_logits(const float* __restrict__ adj) {
    int tid = threadIdx.x;
    int bid = blockIdx.y * 16 + blockIdx.x;
    if (bid < 32)      g_acc[bid * 512 + tid] = 0.f;
    else if (bid < 48) g_r1[(bid - 32) * 512 + tid] = 0.f;
    else if (bid < 64) g_c2[(bid - 48) * 512 + tid] = 0.f;

    int a0 = blockIdx.y * 32, b0 = blockIdx.x * 32;
    int bl = tid >> 4, t = tid & 15;
    int bg = b0 + bl;

    __shared__ ull   Qs[32][16];
    __shared__ float QBs[32][16], RAs[32][16];
    {
        int a = tid >> 4, p = tid & 15;
        float2 v = *((const float2*)(g_Q + (a0 + a) * 32) + p);
        Qs[a][p]  = pk2(v.x, v.y);
        QBs[a][p] = g_QB[(a0 + a) * 16 + p];
        RAs[a][p] = g_RA[(a0 + a) * 16 + p];
    }
    ull wa[16], wb[16];
    {
        const float4* pa = (const float4*)(g_XW1a + (bg * 16 + t) * 32);
        const float4* pb = (const float4*)(g_XW1b + (bg * 16 + t) * 32);
#pragma unroll
        for (int v = 0; v < 8; v++) {
            float4 fa = pa[v], fb = pb[v];
            wa[2 * v] = pk2(fa.x, fa.y); wa[2 * v + 1] = pk2(fa.z, fa.w);
            wb[2 * v] = pk2(fb.x, fb.y); wb[2 * v + 1] = pk2(fb.z, fb.w);
        }
    }
    __syncthreads();

    bool hasT = (t < 15);
    const float* pR = adj + ((long)a0 * 512 + bg) * 15 + t;
    const float* pC = adj + ((long)bg * 512 + a0) * 15 + t;

    for (int al = 0; al < 32; al++) {
        int ag = a0 + al;
        ull acc1 = 0ull, acc2 = 0ull;
        const ulonglong2* qrow = (const ulonglong2*)Qs[al];
#pragma unroll
        for (int j = 0; j < 8; j++) {
            ulonglong2 q = qrow[j];
            ffma2(acc1, q.x, wa[2 * j]);
            ffma2(acc1, q.y, wa[2 * j + 1]);
            ffma2(acc2, q.x, wb[2 * j]);
            ffma2(acc2, q.y, wb[2 * j + 1]);
        }
        float lo, hi;
        upk2(lo, hi, acc1); float p1 = lo + hi;
        upk2(lo, hi, acc2); float p2 = lo + hi;

        float l1p, l2p;
        if (hasT) {
            float ar = pR[al * 7680];
            float ac = pC[al * 15];
            l1p = ar * p1 + ac * QBs[al][t];
            l2p = ac * RAs[al][t] + ar * p2;
        } else {
            bool dg = (ag == bg);
            l1p = dg ? (p1 + QBs[al][15]) : 0.f;
            l2p = dg ? (RAs[al][15] + p2) : 0.f;
        }
#pragma unroll
        for (int o = 8; o; o >>= 1) {
            l1p += __shfl_xor_sync(0xffffffffu, l1p, o);
            l2p += __shfl_xor_sync(0xffffffffu, l2p, o);
        }
        if (t == 0) {
            g_L1[ag * 512 + bg]  = l1p;
            g_L2T[ag * 512 + bg] = l2p;
        }
    }
}

// ---------------- k5: row softmax ----------------
__global__ void k5_softmax() {
    int r = blockIdx.x;
    float* row = (r < 512) ? (g_L1 + r * 512) : (g_L2T + (r - 512) * 512);
    int tid = threadIdx.x;
    __shared__ float red[8];
    float v0 = row[tid], v1 = row[tid + 256];
    float m = fmaxf(v0, v1);
#pragma unroll
    for (int o = 16; o; o >>= 1) m = fmaxf(m, __shfl_xor_sync(0xffffffffu, m, o));
    if ((tid & 31) == 0) red[tid >> 5] = m;
    __syncthreads();
    float bm = red[0];
#pragma unroll
    for (int i = 1; i < 8; i++) bm = fmaxf(bm, red[i]);
    float e0 = __expf(v0 - bm), e1 = __expf(v1 - bm);
    float s = e0 + e1;
#pragma unroll
    for (int o = 16; o; o >>= 1) s += __shfl_xor_sync(0xffffffffu, s, o);
    __syncthreads();
    if ((tid & 31) == 0) red[tid >> 5] = s;
    __syncthreads();
    float bs = red[0] + red[1] + red[2] + red[3] + red[4] + red[5] + red[6] + red[7];
    float inv = 1.0f / bs;
    row[tid] = e0 * inv;
    row[tid + 256] = e1 * inv;
}

// ---------------- k7: fused A-build + register-blocked GEMM + r1/c2 ----------------
// grid (16 ksplits over m, 16 a-tiles of 32), 256 threads, dynamic smem
struct K7S {
    ull   As1p[128][16];   // packed a-pairs, 16B-aligned for ulonglong2 loads
    ull   As2p[128][16];
    float Bs1[128][32];
    float Bs2[128][32];
    float s1s[32][33], s2s[32][33];
    float adjS[32][121];
    float accS[32][33];
};

__global__ void __launch_bounds__(256) k7_fused(const float* __restrict__ adj) {
    extern __shared__ char smem_raw[];
    K7S& S = *reinterpret_cast<K7S*>(smem_raw);
    int m0 = blockIdx.x * 32;
    int a0 = blockIdx.y * 32;
    int tid = threadIdx.x;

#pragma unroll
    for (int j = 0; j < 4; j++) {
        int idx = tid + j * 256;
        int a = idx >> 5, ml = idx & 31;
        S.s1s[a][ml] = g_L1[(a0 + a) * 512 + m0 + ml];
        S.s2s[a][ml] = g_L2T[(a0 + a) * 512 + m0 + ml];
    }
    __syncthreads();

    // r1/c2 partials over this block's m-range
    {
        int a = tid >> 3, tp = tid & 7;
        int t0 = tp * 2;
        int ag = a0 + a;
        bool hasT1 = (t0 + 1 < 15);
        float r0 = 0.f, r1v = 0.f, c0 = 0.f, c1v = 0.f;
        for (int ml = 0; ml < 32; ml++) {
            const float* base = adj + ((long)(m0 + ml) * 512 + ag) * 15;
            float v0 = base[t0];
            float v1 = hasT1 ? base[t0 + 1] : 0.f;
            float w1 = S.s1s[a][ml], w2 = S.s2s[a][ml];
            r0 += w1 * v0; r1v += w1 * v1;
            c0 += w2 * v0; c1v += w2 * v1;
        }
        atomicAdd(&g_r1[ag * 16 + t0], r0);
        atomicAdd(&g_c2[ag * 16 + t0], c0);
        if (hasT1) {
            atomicAdd(&g_r1[ag * 16 + t0 + 1], r1v);
            atomicAdd(&g_c2[ag * 16 + t0 + 1], c1v);
        } else if (ag >= m0 && ag < m0 + 32) {
            atomicAdd(&g_r1[ag * 16 + 15], S.s1s[a][ag - m0]);
            atomicAdd(&g_c2[ag * 16 + 15], S.s2s[a][ag - m0]);
        }
    }

    // thread tile: 4a x 4d, 4-way k-split within block
    int pos = tid & 63, ksub = tid >> 6;
    int a4 = (pos & 7) * 4;       // a base (pair index a4/2, 16B-aligned)
    int d4 = (pos >> 3) * 4;      // d base
    ull acc[2][4];
#pragma unroll
    for (int p = 0; p < 2; p++)
#pragma unroll
        for (int j = 0; j < 4; j++) acc[p][j] = 0ull;

    for (int mc = 0; mc < 4; mc++) {
        int mb = m0 + mc * 8;
        __syncthreads();
        // stage adj rows: 32 a x 120 contiguous floats
        for (int idx = tid; idx < 960; idx += 256) {
            int a = idx / 30, r4 = (idx - a * 30) * 4;
            float4 v = *(const float4*)(adj + (long)(a0 + a) * 7680 + mb * 15 + r4);
            float* dst = &S.adjS[a][r4];
            dst[0] = v.x; dst[1] = v.y; dst[2] = v.z; dst[3] = v.w;
        }
        // stage B panels (float4)
        for (int idx = tid; idx < 1024; idx += 256) {
            int kk = idx >> 3, dd = (idx & 7) * 4;
            *(float4*)&S.Bs1[kk][dd] = *(const float4*)(g_XW2a + (mb * 16 + kk) * 32 + dd);
            *(float4*)&S.Bs2[kk][dd] = *(const float4*)(g_XW2b + (mb * 16 + kk) * 32 + dd);
        }
        __syncthreads();
        // build packed A tiles
#pragma unroll
        for (int j = 0; j < 8; j++) {
            int idx = tid + j * 256;
            int ap = idx & 15, kk = idx >> 4;
            int ml = kk >> 4, t = kk & 15;
            float v1[2], v2[2];
#pragma unroll
            for (int l = 0; l < 2; l++) {
                int a = 2 * ap + l;
                float sv1 = S.s1s[a][mc * 8 + ml], sv2 = S.s2s[a][mc * 8 + ml];
                if (t < 15) {
                    float av = S.adjS[a][ml * 15 + t];
                    v1[l] = sv1 * av; v2[l] = sv2 * av;
                } else {
                    bool dg = (mb + ml == a0 + a);
                    v1[l] = dg ? sv1 : 0.f;
                    v2[l] = dg ? sv2 : 0.f;
                }
            }
            S.As1p[kk][ap] = pk2(v1[0], v1[1]);
            S.As2p[kk][ap] = pk2(v2[0], v2[1]);
        }
        __syncthreads();
        // inner: 32 kk per thread
        int kk0 = ksub * 32;
        const ull*   pA1 = &S.As1p[0][(pos & 7) * 2];
        const ull*   pA2 = &S.As2p[0][(pos & 7) * 2];
        const float* pB1 = &S.Bs1[0][d4];
        const float* pB2 = &S.Bs2[0][d4];
#pragma unroll 8
        for (int kk = kk0; kk < kk0 + 32; kk++) {
            ulonglong2 A1 = *(const ulonglong2*)(pA1 + kk * 16);
            float4 b1 = *(const float4*)(pB1 + kk * 32);
            ull bx = pk2(b1.x, b1.x), by = pk2(b1.y, b1.y);
            ull bz = pk2(b1.z, b1.z), bw = pk2(b1.w, b1.w);
            ffma2(acc[0][0], A1.x, bx); ffma2(acc[0][1], A1.x, by);
            ffma2(acc[0][2], A1.x, bz); ffma2(acc[0][3], A1.x, bw);
            ffma2(acc[1][0], A1.y, bx); ffma2(acc[1][1], A1.y, by);
            ffma2(acc[1][2], A1.y, bz); ffma2(acc[1][3], A1.y, bw);
            ulonglong2 A2 = *(const ulonglong2*)(pA2 + kk * 16);
            float4 b2 = *(const float4*)(pB2 + kk * 32);
            ull cx = pk2(b2.x, b2.x), cy = pk2(b2.y, b2.y);
            ull cz = pk2(b2.z, b2.z), cw = pk2(b2.w, b2.w);
            ffma2(acc[0][0], A2.x, cx); ffma2(acc[0][1], A2.x, cy);
            ffma2(acc[0][2], A2.x, cz); ffma2(acc[0][3], A2.x, cw);
            ffma2(acc[1][0], A2.y, cx); ffma2(acc[1][1], A2.y, cy);
            ffma2(acc[1][2], A2.y, cz); ffma2(acc[1][3], A2.y, cw);
        }
    }

    // merge 4 k-split partials in smem (pass 0 writes, 1-3 add)
    for (int s = 0; s < 4; s++) {
        __syncthreads();
        if (ksub == s) {
#pragma unroll
            for (int p = 0; p < 2; p++)
#pragma unroll
                for (int j = 0; j < 4; j++) {
                    float lo, hi; upk2(lo, hi, acc[p][j]);
                    int aa = a4 + 2 * p, dd = d4 + j;
                    if (s == 0) { S.accS[aa][dd] = lo; S.accS[aa + 1][dd] = hi; }
                    else        { S.accS[aa][dd] += lo; S.accS[aa + 1][dd] += hi; }
                }
        }
    }
    __syncthreads();
    for (int idx = tid; idx < 1024; idx += 256) {
        int aa = idx >> 5, dd = idx & 31;
        atomicAdd(&g_acc[(a0 + aa) * 32 + dd], S.accS[aa][dd]);
    }
}

// ---------------- k7b: epilogue ----------------
__global__ void k7b_epilogue(float* __restrict__ out) {
    int idx = blockIdx.x * 256 + threadIdx.x;
    int n = idx >> 5, d = idx & 31;
    float acc = g_acc[idx];
    const float* r1 = g_r1 + n * 16;
    const float* c2 = g_c2 + n * 16;
    const float* wb = g_XW2b + n * 512 + d;
    const float* wa = g_XW2a + n * 512 + d;
#pragma unroll
    for (int t = 0; t < 16; t++) acc += r1[t] * wb[t * 32] + c2[t] * wa[t * 32];
    out[idx] = fmaxf(acc, 0.2f * acc);
}

// ---------------- launch ----------------
extern "C" void kernel_launch(void* const* d_in, const int* in_sizes, int n_in,
                              void* d_out, int out_size) {
    const float* x   = (const float*)d_in[0];
    const float* adj = (const float*)d_in[1];
    const float* W1  = (const float*)d_in[2];
    const float* W2  = (const float*)d_in[3];
    const float* W3  = (const float*)d_in[4];
    float* out = (float*)d_out;
    (void)in_sizes; (void)n_in; (void)out_size;

    cudaFuncSetAttribute(k7_fused, cudaFuncAttributeMaxDynamicSharedMemorySize,
                         (int)sizeof(K7S));

    k1_precompute<<<128, 256>>>(x, W1, W2, W3);
    k2_logits<<<dim3(16, 16), 512>>>(adj);
    k5_softmax<<<1024, 256>>>();
    k7_fused<<<dim3(16, 16), 256, sizeof(K7S)>>>(adj);
    k7b_epilogue<<<64, 256>>>(out);
}